// round 13
// baseline (speedup 1.0000x reference)
#include <cuda_runtime.h>
#include <cuda_bf16.h>
#include <cstdint>

#define BB 8
#define SS 4096
#define EE 768
#define JMAX 2048
#define INV_SQRT_DK 0.03608439182435161f

#define NX ((size_t)BB * SS * EE)     // 25.2M
#define NK ((size_t)BB * JMAX * EE)   // 12.6M
#define NP ((size_t)BB * SS * JMAX)   // 67.1M

// ---------------- scratch (device globals; no allocations allowed) ----------
__device__ __nv_bfloat16 g_Xhi[NX], g_Xlo[NX];
__device__ __nv_bfloat16 g_Wqh[EE * EE], g_Wql[EE * EE];
__device__ __nv_bfloat16 g_Wkh[EE * EE], g_Wkl[EE * EE];
__device__ __nv_bfloat16 g_Qhi[NX], g_Qlo[NX];
__device__ __nv_bfloat16 g_Khi[NK], g_Klo[NK];
__device__ __nv_bfloat16 g_Vth[NK], g_Vtl[NK];   // [b][e][token] transposed V splits
__device__ __nv_bfloat16 g_Phi[NP], g_Plo[NP];   // unnormalized exp splits
__device__ float g_partial[(size_t)BB * SS * 32]; // per-(row, ctile, wn) sums

// ---------------- helpers ----------------------------------------------------
__device__ __forceinline__ uint32_t smem_to_u32(const void* p) {
    uint32_t a;
    asm("{ .reg .u64 t; cvta.to.shared.u64 t, %1; cvt.u32.u64 %0, t; }" : "=r"(a) : "l"(p));
    return a;
}
__device__ __forceinline__ int seq_first(const int* __restrict__ s, int b) {
    const bool is64 = (s[1] == 0);
    int v = is64 ? s[4 * b] : s[2 * b];
    if (v < 1) v = 1;
    if (v > JMAX) v = JMAX;
    return v;
}
__device__ __forceinline__ void split2(float v, __nv_bfloat16& h, __nv_bfloat16& l) {
    h = __float2bfloat16(v);
    l = __float2bfloat16(v - __bfloat162float(h));
}
__device__ __forceinline__ uint32_t packbf(__nv_bfloat16 a, __nv_bfloat16 b) {
    return (uint32_t)__bfloat16_as_ushort(a) | ((uint32_t)__bfloat16_as_ushort(b) << 16);
}

__device__ __forceinline__ void ldsm4(uint32_t* d, uint32_t a) {
    asm volatile("ldmatrix.sync.aligned.m8n8.x4.shared.b16 {%0,%1,%2,%3}, [%4];"
                 : "=r"(d[0]), "=r"(d[1]), "=r"(d[2]), "=r"(d[3]) : "r"(a));
}
__device__ __forceinline__ void mma_bf16(float* c, const uint32_t* a, uint32_t b0, uint32_t b1) {
    asm volatile(
        "mma.sync.aligned.m16n8k16.row.col.f32.bf16.bf16.f32 "
        "{%0,%1,%2,%3}, {%4,%5,%6,%7}, {%8,%9}, {%0,%1,%2,%3};"
        : "+f"(c[0]), "+f"(c[1]), "+f"(c[2]), "+f"(c[3])
        : "r"(a[0]), "r"(a[1]), "r"(a[2]), "r"(a[3]), "r"(b0), "r"(b1));
}
#define CP_ASYNC16(sa, ga) \
    asm volatile("cp.async.cg.shared.global [%0], [%1], 16;" :: "r"(sa), "l"(ga) : "memory")
#define CP_COMMIT() asm volatile("cp.async.commit_group;" ::: "memory")
#define CP_WAIT(n)  asm volatile("cp.async.wait_group %0;" :: "n"(n) : "memory")

// ---------------- kernel: fp32 -> (hi, lo) bf16 splits ------------------------
__global__ __launch_bounds__(256) void split_sel(const float* __restrict__ src,
                                                 int sel, size_t n4)
{
    size_t i = (size_t)blockIdx.x * 256 + threadIdx.x;
    if (i >= n4) return;
    __nv_bfloat16 *dh, *dl;
    if (sel == 0)      { dh = g_Xhi; dl = g_Xlo; }
    else if (sel == 1) { dh = g_Wqh; dl = g_Wql; }
    else               { dh = g_Wkh; dl = g_Wkl; }
    float4 v = ((const float4*)src)[i];
    __nv_bfloat16 h0, l0, h1, l1, h2, l2, h3, l3;
    split2(v.x, h0, l0); split2(v.y, h1, l1);
    split2(v.z, h2, l2); split2(v.w, h3, l3);
    ((uint2*)dh)[i] = make_uint2(packbf(h0, h1), packbf(h2, h3));
    ((uint2*)dl)[i] = make_uint2(packbf(l0, l1), packbf(l2, l3));
}

// ---------------- generic split-bf16 NT GEMM on mma.sync ---------------------
#define TSTRIDE 80
#define TILE_SM (128 * TSTRIDE)          // 10240
#define STAGE_SM (4 * TILE_SM)           // 40960
#define SMEM_TC (2 * STAGE_SM)           // 81920

#define MODE_PROJQ 0
#define MODE_PROJK 1
#define MODE_SCORE 2
#define MODE_PV    3

__global__ __launch_bounds__(128, 2) void tc_gemm(int mode, const int* __restrict__ seq,
                                                  const float* __restrict__ bias,
                                                  float* __restrict__ Hout, int bbase)
{
    const int n0 = blockIdx.x << 7;
    int b = 0, first = 0, Kdim = EE;
    size_t arow, brow, orow;
    int lda, ldb, ldo = EE;
    const __nv_bfloat16 *Ah, *Al, *Bh, *Bl;
    float* outF = nullptr;
    __nv_bfloat16 *oHi = nullptr, *oLo = nullptr;
    bool addb = false;

    if (mode == MODE_PROJQ) {
        arow = (size_t)blockIdx.y << 7; brow = n0; orow = arow;
        Ah = g_Xhi; Al = g_Xlo; lda = EE; Bh = g_Wqh; Bl = g_Wql; ldb = EE;
        oHi = g_Qhi; oLo = g_Qlo; ldo = EE; addb = true;
    } else if (mode == MODE_PROJK) {
        b = blockIdx.y >> 4;
        int tloc = (blockIdx.y & 15) << 7;
        first = seq_first(seq, b);
        if (tloc >= first) return;
        arow = (size_t)b * SS + tloc; brow = n0; orow = (size_t)b * JMAX + tloc;
        Ah = g_Xhi; Al = g_Xlo; lda = EE; Bh = g_Wkh; Bl = g_Wkl; ldb = EE;
        oHi = g_Khi; oLo = g_Klo; ldo = EE; addb = true;
    } else if (mode == MODE_SCORE) {
        b = blockIdx.z + bbase; first = seq_first(seq, b);
        if (n0 >= first) return;
        arow = (size_t)b * SS + ((size_t)blockIdx.y << 7);
        brow = (size_t)b * JMAX + n0;
        Ah = g_Qhi; Al = g_Qlo; lda = EE; Bh = g_Khi; Bl = g_Klo; ldb = EE;
        oHi = g_Phi; oLo = g_Plo; ldo = JMAX; orow = arow;
    } else { // MODE_PV
        b = blockIdx.z + bbase; first = seq_first(seq, b);
        Kdim = (first + 63) & ~63;
        arow = (size_t)b * SS + ((size_t)blockIdx.y << 7);
        brow = (size_t)b * EE + n0;
        Ah = g_Phi; Al = g_Plo; lda = JMAX; Bh = g_Vth; Bl = g_Vtl; ldb = JMAX;
        outF = Hout; ldo = EE; orow = arow;
    }

    extern __shared__ char smem[];
    const uint32_t sbase = smem_to_u32(smem);
    const int tid  = threadIdx.x;
    const int lane = tid & 31, wid = tid >> 5;
    const int wm = wid >> 1, wn = wid & 1;          // 2 x 2 warp grid, warp tile 64x64

    const char* gsrc[4] = { (const char*)(Ah + arow * lda), (const char*)(Al + arow * lda),
                            (const char*)(Bh + brow * ldb), (const char*)(Bl + brow * ldb) };
    const size_t ldby[4] = { (size_t)lda * 2, (size_t)lda * 2,
                             (size_t)ldb * 2, (size_t)ldb * 2 };

    auto load_stage = [&](int s, int ki) {
        const size_t k0b = (size_t)ki * 64;          // 32 bf16 = 64 bytes
        const uint32_t sb = sbase + s * STAGE_SM;
        #pragma unroll
        for (int j = 0; j < 16; j++) {
            int t = tid + j * 128;                   // 2048 chunks of 16B
            int tile = t >> 9, row = (t >> 2) & 127, c = t & 3;
            uint32_t sa = sb + tile * TILE_SM + row * TSTRIDE + c * 16;
            const char* ga = gsrc[tile] + (size_t)row * ldby[tile] + k0b + c * 16;
            CP_ASYNC16(sa, ga);
        }
    };

    float acc[4][8][4];
    #pragma unroll
    for (int mt = 0; mt < 4; mt++)
        #pragma unroll
        for (int nt = 0; nt < 8; nt++)
            #pragma unroll
            for (int r = 0; r < 4; r++) acc[mt][nt][r] = 0.f;

    const int kt = Kdim >> 5;                        // BK = 32

    load_stage(0, 0);
    CP_COMMIT();

    for (int i = 0; i < kt; i++) {
        const int cur = i & 1;
        if (i + 1 < kt) { load_stage(cur ^ 1, i + 1); CP_COMMIT(); CP_WAIT(1); }
        else            { CP_WAIT(0); }
        __syncthreads();

        const uint32_t sb = sbase + cur * STAGE_SM;
        #pragma unroll
        for (int ks = 0; ks < 2; ks++) {             // two k16 halves of BK=32
            uint32_t ah[4][4], alr[4][4];
            #pragma unroll
            for (int mt = 0; mt < 4; mt++) {
                uint32_t ra = sb + (wm * 64 + mt * 16 + (lane & 15)) * TSTRIDE
                            + ks * 32 + ((lane >> 4) << 4);
                ldsm4(ah[mt],  ra);
                ldsm4(alr[mt], ra + TILE_SM);
            }
            uint32_t bh4[4][4], bl4[4][4];
            #pragma unroll
            for (int nt2 = 0; nt2 < 4; nt2++) {
                uint32_t rb = sb + 2 * TILE_SM
                            + (wn * 64 + nt2 * 16 + ((lane & 7) + ((lane >> 4) << 3))) * TSTRIDE
                            + ks * 32 + (((lane >> 3) & 1) << 4);
                ldsm4(bh4[nt2], rb);
                ldsm4(bl4[nt2], rb + TILE_SM);
            }
            #pragma unroll
            for (int p = 0; p < 3; p++) {
                #pragma unroll
                for (int mt = 0; mt < 4; mt++)
                    #pragma unroll
                    for (int nt2 = 0; nt2 < 4; nt2++)
                        #pragma unroll
                        for (int nn = 0; nn < 2; nn++) {
                            float* c = acc[mt][nt2 * 2 + nn];
                            const uint32_t* a = (p == 2) ? alr[mt] : ah[mt];
                            const uint32_t* bb = (p == 1) ? bl4[nt2] : bh4[nt2];
                            mma_bf16(c, a, bb[2 * nn], bb[2 * nn + 1]);
                        }
            }
        }
        __syncthreads();
    }

    // epilogue
    const int grp = lane >> 2, tig = lane & 3;
    #pragma unroll
    for (int mt = 0; mt < 4; mt++) {
        #pragma unroll
        for (int half = 0; half < 2; half++) {
            const size_t row = orow + wm * 64 + mt * 16 + grp + half * 8;
            if (mode == MODE_SCORE) {
                // exp + split write + deterministic partial row sum
                float rsum = 0.f;
                #pragma unroll
                for (int nt = 0; nt < 8; nt++) {
                    const int col = n0 + wn * 64 + nt * 8 + tig * 2;
                    float p0 = 0.f, p1 = 0.f;
                    if (col >= 1 && col < first) {
                        p0 = __expf(acc[mt][nt][half * 2 + 0] * INV_SQRT_DK);
                        rsum += p0;
                    }
                    if (col + 1 >= 1 && col + 1 < first) {
                        p1 = __expf(acc[mt][nt][half * 2 + 1] * INV_SQRT_DK);
                        rsum += p1;
                    }
                    __nv_bfloat16 h0, l0, h1, l1;
                    split2(p0, h0, l0); split2(p1, h1, l1);
                    *(uint32_t*)&oHi[row * ldo + col] = packbf(h0, h1);
                    *(uint32_t*)&oLo[row * ldo + col] = packbf(l0, l1);
                }
                rsum += __shfl_xor_sync(0xffffffff, rsum, 1);
                rsum += __shfl_xor_sync(0xffffffff, rsum, 2);
                if (tig == 0)
                    g_partial[row * 32 + (size_t)blockIdx.x * 2 + wn] = rsum;
            } else if (outF) {   // PV: fold partials -> inv_l, then scaled write
                const float* pp = &g_partial[row * 32];
                const int np = 2 * ((first + 127) >> 7);
                float s = 0.f;
                for (int i2 = tig; i2 < np; i2 += 4) s += pp[i2];
                s += __shfl_xor_sync(0xffffffff, s, 1);
                s += __shfl_xor_sync(0xffffffff, s, 2);
                const float rsc = 1.0f / fmaxf(s, 1e-30f);
                #pragma unroll
                for (int nt = 0; nt < 8; nt++) {
                    const int col = n0 + wn * 64 + nt * 8 + tig * 2;
                    *(float2*)&outF[row * ldo + col] =
                        make_float2(acc[mt][nt][half * 2 + 0] * rsc,
                                    acc[mt][nt][half * 2 + 1] * rsc);
                }
            } else {             // projections
                #pragma unroll
                for (int nt = 0; nt < 8; nt++) {
                    const int col = n0 + wn * 64 + nt * 8 + tig * 2;
                    float v0 = acc[mt][nt][half * 2 + 0];
                    float v1 = acc[mt][nt][half * 2 + 1];
                    if (addb) { v0 += bias[col]; v1 += bias[col + 1]; }
                    __nv_bfloat16 h0, l0, h1, l1;
                    split2(v0, h0, l0); split2(v1, h1, l1);
                    *(uint32_t*)&oHi[row * ldo + col] = packbf(h0, h1);
                    *(uint32_t*)&oLo[row * ldo + col] = packbf(l0, l1);
                }
            }
        }
    }
}

// ---------------- kernel: V projection (SIMT fp32), transposed split output --
__global__ __launch_bounds__(256) void v_gemm(
    const float* __restrict__ X, const float* __restrict__ W,
    const float* __restrict__ bias, const int* __restrict__ seq)
{
    const int tid = threadIdx.x;
    const int tx = tid & 15;
    const int ty = tid >> 4;

    const int b    = blockIdx.y >> 4;
    const int tloc = (blockIdx.y & 15) << 7;
    const int col0 = blockIdx.x << 7;
    const int first = seq_first(seq, b);
    if (tloc >= first) return;

    const int xrow0 = b * SS + tloc;

    __shared__ float As[16][128];
    __shared__ float Bs[16][128];

    float acc[8][8];
    #pragma unroll
    for (int i = 0; i < 8; i++)
        #pragma unroll
        for (int j = 0; j < 8; j++) acc[i][j] = 0.f;

    for (int k0 = 0; k0 < EE; k0 += 16) {
        #pragma unroll
        for (int v = tid; v < 512; v += 256) {
            int r = v >> 2;
            int c = (v & 3) << 2;
            float4 a = *(const float4*)&X[(size_t)(xrow0 + r) * EE + k0 + c];
            As[c + 0][r] = a.x; As[c + 1][r] = a.y;
            As[c + 2][r] = a.z; As[c + 3][r] = a.w;
            float4 wv = *(const float4*)&W[(size_t)(col0 + r) * EE + k0 + c];
            Bs[c + 0][r] = wv.x; Bs[c + 1][r] = wv.y;
            Bs[c + 2][r] = wv.z; Bs[c + 3][r] = wv.w;
        }
        __syncthreads();

        #pragma unroll
        for (int kk = 0; kk < 16; kk++) {
            float4 a0 = *(const float4*)&As[kk][ty * 8];
            float4 a1 = *(const float4*)&As[kk][ty * 8 + 4];
            float4 b0 = *(const float4*)&Bs[kk][tx * 8];
            float4 b1 = *(const float4*)&Bs[kk][tx * 8 + 4];
            float av[8] = {a0.x, a0.y, a0.z, a0.w, a1.x, a1.y, a1.z, a1.w};
            float bv[8] = {b0.x, b0.y, b0.z, b0.w, b1.x, b1.y, b1.z, b1.w};
            #pragma unroll
            for (int i = 0; i < 8; i++)
                #pragma unroll
                for (int j = 0; j < 8; j++)
                    acc[i][j] = fmaf(av[i], bv[j], acc[i][j]);
        }
        __syncthreads();
    }

    const int tok0 = tloc + ty * 8;
    #pragma unroll
    for (int j = 0; j < 8; j++) {
        const int e = col0 + tx * 8 + j;
        const float be = bias[e];
        uint32_t hu[4], lu[4];
        #pragma unroll
        for (int pr = 0; pr < 4; pr++) {
            __nv_bfloat16 h0, l0, h1, l1;
            split2(acc[pr * 2 + 0][j] + be, h0, l0);
            split2(acc[pr * 2 + 1][j] + be, h1, l1);
            hu[pr] = packbf(h0, h1);
            lu[pr] = packbf(l0, l1);
        }
        const size_t off = ((size_t)b * EE + e) * JMAX + tok0;
        *(uint4*)&g_Vth[off] = make_uint4(hu[0], hu[1], hu[2], hu[3]);
        *(uint4*)&g_Vtl[off] = make_uint4(lu[0], lu[1], lu[2], lu[3]);
    }
}

// ---------------------------------------------------------------------------
extern "C" void kernel_launch(void* const* d_in, const int* in_sizes, int n_in,
                              void* d_out, int out_size)
{
    const float* ebd = (const float*)d_in[0];
    const int*   seq = (const int*)d_in[1];
    const float* Wq = (const float*)d_in[2];
    const float* bq = (const float*)d_in[3];
    const float* Wk = (const float*)d_in[4];
    const float* bk = (const float*)d_in[5];
    const float* Wv = (const float*)d_in[6];
    const float* bv = (const float*)d_in[7];
    float* H = (float*)d_out;

    static cudaStream_t s2 = nullptr;
    static cudaEvent_t evFork = nullptr, evSplit = nullptr;
    static cudaEvent_t evK = nullptr, evQ = nullptr, evChain = nullptr;
    if (!s2) {
        cudaFuncSetAttribute(tc_gemm, cudaFuncAttributeMaxDynamicSharedMemorySize, SMEM_TC);
        cudaStreamCreateWithFlags(&s2, cudaStreamNonBlocking);
        cudaEventCreateWithFlags(&evFork, cudaEventDisableTiming);
        cudaEventCreateWithFlags(&evSplit, cudaEventDisableTiming);
        cudaEventCreateWithFlags(&evK, cudaEventDisableTiming);
        cudaEventCreateWithFlags(&evQ, cudaEventDisableTiming);
        cudaEventCreateWithFlags(&evChain, cudaEventDisableTiming);
    }

    // fork: v_gemm (no deps) on side stream
    cudaEventRecord(evFork, 0);
    cudaStreamWaitEvent(s2, evFork, 0);
    v_gemm<<<dim3(EE / 128, BB * (JMAX / 128)), 256, 0, s2>>>(ebd, Wv, bv, seq);

    // 0) fp32 -> split bf16 for X, Wq, Wk (main stream)
    {
        size_t n4 = NX / 4;
        split_sel<<<(unsigned)((n4 + 255) / 256), 256>>>(ebd, 0, n4);
        size_t w4 = (size_t)EE * EE / 4;
        split_sel<<<(unsigned)((w4 + 255) / 256), 256>>>(Wq, 1, w4);
        split_sel<<<(unsigned)((w4 + 255) / 256), 256>>>(Wk, 2, w4);
    }
    cudaEventRecord(evSplit, 0);

    // PROJK on side stream (after splits + v_gemm), PROJQ on main — overlap
    cudaStreamWaitEvent(s2, evSplit, 0);
    tc_gemm<<<dim3(EE / 128, BB * (JMAX / 128), 1), 128, SMEM_TC, s2>>>(MODE_PROJK, seq, bk, nullptr, 0);
    cudaEventRecord(evK, s2);

    tc_gemm<<<dim3(EE / 128, BB * SS / 128, 1), 128, SMEM_TC>>>(MODE_PROJQ, seq, bq, nullptr, 0);
    cudaEventRecord(evQ, 0);

    // cross-join: main needs K (and V — ordered before PROJK on s2); s2 needs Q
    cudaStreamWaitEvent(0, evK, 0);
    cudaStreamWaitEvent(s2, evQ, 0);

    // half-batch pipelined attention: batches 0-3 on main, 4-7 on s2
    tc_gemm<<<dim3(JMAX / 128, SS / 128, 4), 128, SMEM_TC>>>(MODE_SCORE, seq, nullptr, nullptr, 0);
    tc_gemm<<<dim3(EE / 128, SS / 128, 4), 128, SMEM_TC>>>(MODE_PV, seq, nullptr, H, 0);

    tc_gemm<<<dim3(JMAX / 128, SS / 128, 4), 128, SMEM_TC, s2>>>(MODE_SCORE, seq, nullptr, nullptr, 4);
    tc_gemm<<<dim3(EE / 128, SS / 128, 4), 128, SMEM_TC, s2>>>(MODE_PV, seq, nullptr, H, 4);

    // join s2 back to main
    cudaEventRecord(evChain, s2);
    cudaStreamWaitEvent(0, evChain, 0);
}

// round 14
// speedup vs baseline: 1.0034x; 1.0034x over previous
#include <cuda_runtime.h>
#include <cuda_bf16.h>
#include <cstdint>

#define BB 8
#define SS 4096
#define EE 768
#define JMAX 2048
#define INV_SQRT_DK 0.03608439182435161f

#define NX ((size_t)BB * SS * EE)     // 25.2M
#define NK ((size_t)BB * JMAX * EE)   // 12.6M
#define NP ((size_t)BB * SS * JMAX)   // 67.1M

// ---------------- scratch (device globals; no allocations allowed) ----------
__device__ __nv_bfloat16 g_Xhi[NX], g_Xlo[NX];
__device__ __nv_bfloat16 g_Wqh[EE * EE], g_Wql[EE * EE];
__device__ __nv_bfloat16 g_Wkh[EE * EE], g_Wkl[EE * EE];
__device__ __nv_bfloat16 g_Qhi[NX], g_Qlo[NX];
__device__ __nv_bfloat16 g_Khi[NK], g_Klo[NK];
__device__ __nv_bfloat16 g_Vth[NK], g_Vtl[NK];   // [b][e][token] transposed V splits
__device__ __nv_bfloat16 g_Phi[NP], g_Plo[NP];   // unnormalized exp splits
__device__ float g_partial[(size_t)BB * SS * 32]; // per-(row, ctile, wn) sums

// ---------------- helpers ----------------------------------------------------
__device__ __forceinline__ uint32_t smem_to_u32(const void* p) {
    uint32_t a;
    asm("{ .reg .u64 t; cvta.to.shared.u64 t, %1; cvt.u32.u64 %0, t; }" : "=r"(a) : "l"(p));
    return a;
}
__device__ __forceinline__ int seq_first(const int* __restrict__ s, int b) {
    const bool is64 = (s[1] == 0);
    int v = is64 ? s[4 * b] : s[2 * b];
    if (v < 1) v = 1;
    if (v > JMAX) v = JMAX;
    return v;
}
__device__ __forceinline__ void split2(float v, __nv_bfloat16& h, __nv_bfloat16& l) {
    h = __float2bfloat16(v);
    l = __float2bfloat16(v - __bfloat162float(h));
}
__device__ __forceinline__ uint32_t packbf(__nv_bfloat16 a, __nv_bfloat16 b) {
    return (uint32_t)__bfloat16_as_ushort(a) | ((uint32_t)__bfloat16_as_ushort(b) << 16);
}

__device__ __forceinline__ void ldsm4(uint32_t* d, uint32_t a) {
    asm volatile("ldmatrix.sync.aligned.m8n8.x4.shared.b16 {%0,%1,%2,%3}, [%4];"
                 : "=r"(d[0]), "=r"(d[1]), "=r"(d[2]), "=r"(d[3]) : "r"(a));
}
__device__ __forceinline__ void mma_bf16(float* c, const uint32_t* a, uint32_t b0, uint32_t b1) {
    asm volatile(
        "mma.sync.aligned.m16n8k16.row.col.f32.bf16.bf16.f32 "
        "{%0,%1,%2,%3}, {%4,%5,%6,%7}, {%8,%9}, {%0,%1,%2,%3};"
        : "+f"(c[0]), "+f"(c[1]), "+f"(c[2]), "+f"(c[3])
        : "r"(a[0]), "r"(a[1]), "r"(a[2]), "r"(a[3]), "r"(b0), "r"(b1));
}
#define CP_ASYNC16(sa, ga) \
    asm volatile("cp.async.cg.shared.global [%0], [%1], 16;" :: "r"(sa), "l"(ga) : "memory")
#define CP_COMMIT() asm volatile("cp.async.commit_group;" ::: "memory")
#define CP_WAIT(n)  asm volatile("cp.async.wait_group %0;" :: "n"(n) : "memory")

// ---------------- kernel: fp32 -> (hi, lo) bf16 splits ------------------------
__global__ __launch_bounds__(256) void split_sel(const float* __restrict__ src,
                                                 int sel, size_t n4)
{
    size_t i = (size_t)blockIdx.x * 256 + threadIdx.x;
    if (i >= n4) return;
    __nv_bfloat16 *dh, *dl;
    if (sel == 0)      { dh = g_Xhi; dl = g_Xlo; }
    else if (sel == 1) { dh = g_Wqh; dl = g_Wql; }
    else               { dh = g_Wkh; dl = g_Wkl; }
    float4 v = ((const float4*)src)[i];
    __nv_bfloat16 h0, l0, h1, l1, h2, l2, h3, l3;
    split2(v.x, h0, l0); split2(v.y, h1, l1);
    split2(v.z, h2, l2); split2(v.w, h3, l3);
    ((uint2*)dh)[i] = make_uint2(packbf(h0, h1), packbf(h2, h3));
    ((uint2*)dl)[i] = make_uint2(packbf(l0, l1), packbf(l2, l3));
}

// ---------------- generic split-bf16 NT GEMM on mma.sync ---------------------
#define TSTRIDE 80
#define TILE_SM (128 * TSTRIDE)          // 10240
#define STAGE_SM (4 * TILE_SM)           // 40960
#define SMEM_TC (2 * STAGE_SM)           // 81920

#define MODE_PROJQ 0
#define MODE_PROJK 1
#define MODE_SCORE 2
#define MODE_PV    3

__global__ __launch_bounds__(128, 2) void tc_gemm(int mode, const int* __restrict__ seq,
                                                  const float* __restrict__ bias,
                                                  float* __restrict__ Hout)
{
    const int n0 = blockIdx.x << 7;
    int b = 0, first = 0, Kdim = EE;
    size_t arow, brow, orow;
    int lda, ldb, ldo = EE;
    const __nv_bfloat16 *Ah, *Al, *Bh, *Bl;
    float* outF = nullptr;
    __nv_bfloat16 *oHi = nullptr, *oLo = nullptr;
    bool addb = false;

    if (mode == MODE_PROJQ) {
        arow = (size_t)blockIdx.y << 7; brow = n0; orow = arow;
        Ah = g_Xhi; Al = g_Xlo; lda = EE; Bh = g_Wqh; Bl = g_Wql; ldb = EE;
        oHi = g_Qhi; oLo = g_Qlo; ldo = EE; addb = true;
    } else if (mode == MODE_PROJK) {
        b = blockIdx.y >> 4;
        int tloc = (blockIdx.y & 15) << 7;
        first = seq_first(seq, b);
        if (tloc >= first) return;
        arow = (size_t)b * SS + tloc; brow = n0; orow = (size_t)b * JMAX + tloc;
        Ah = g_Xhi; Al = g_Xlo; lda = EE; Bh = g_Wkh; Bl = g_Wkl; ldb = EE;
        oHi = g_Khi; oLo = g_Klo; ldo = EE; addb = true;
    } else if (mode == MODE_SCORE) {
        b = blockIdx.z; first = seq_first(seq, b);
        if (n0 >= first) return;
        arow = (size_t)b * SS + ((size_t)blockIdx.y << 7);
        brow = (size_t)b * JMAX + n0;
        Ah = g_Qhi; Al = g_Qlo; lda = EE; Bh = g_Khi; Bl = g_Klo; ldb = EE;
        oHi = g_Phi; oLo = g_Plo; ldo = JMAX; orow = arow;
    } else { // MODE_PV
        b = blockIdx.z; first = seq_first(seq, b);
        Kdim = (first + 63) & ~63;
        arow = (size_t)b * SS + ((size_t)blockIdx.y << 7);
        brow = (size_t)b * EE + n0;
        Ah = g_Phi; Al = g_Plo; lda = JMAX; Bh = g_Vth; Bl = g_Vtl; ldb = JMAX;
        outF = Hout; ldo = EE; orow = arow;
    }

    extern __shared__ char smem[];
    const uint32_t sbase = smem_to_u32(smem);
    const int tid  = threadIdx.x;
    const int lane = tid & 31, wid = tid >> 5;
    const int wm = wid >> 1, wn = wid & 1;          // 2 x 2 warp grid, warp tile 64x64

    const char* gsrc[4] = { (const char*)(Ah + arow * lda), (const char*)(Al + arow * lda),
                            (const char*)(Bh + brow * ldb), (const char*)(Bl + brow * ldb) };
    const size_t ldby[4] = { (size_t)lda * 2, (size_t)lda * 2,
                             (size_t)ldb * 2, (size_t)ldb * 2 };

    auto load_stage = [&](int s, int ki) {
        const size_t k0b = (size_t)ki * 64;          // 32 bf16 = 64 bytes
        const uint32_t sb = sbase + s * STAGE_SM;
        #pragma unroll
        for (int j = 0; j < 16; j++) {
            int t = tid + j * 128;                   // 2048 chunks of 16B
            int tile = t >> 9, row = (t >> 2) & 127, c = t & 3;
            uint32_t sa = sb + tile * TILE_SM + row * TSTRIDE + c * 16;
            const char* ga = gsrc[tile] + (size_t)row * ldby[tile] + k0b + c * 16;
            CP_ASYNC16(sa, ga);
        }
    };

    float acc[4][8][4];
    #pragma unroll
    for (int mt = 0; mt < 4; mt++)
        #pragma unroll
        for (int nt = 0; nt < 8; nt++)
            #pragma unroll
            for (int r = 0; r < 4; r++) acc[mt][nt][r] = 0.f;

    const int kt = Kdim >> 5;                        // BK = 32

    load_stage(0, 0);
    CP_COMMIT();

    for (int i = 0; i < kt; i++) {
        const int cur = i & 1;
        if (i + 1 < kt) { load_stage(cur ^ 1, i + 1); CP_COMMIT(); CP_WAIT(1); }
        else            { CP_WAIT(0); }
        __syncthreads();

        const uint32_t sb = sbase + cur * STAGE_SM;
        #pragma unroll
        for (int ks = 0; ks < 2; ks++) {             // two k16 halves of BK=32
            uint32_t ah[4][4], alr[4][4];
            #pragma unroll
            for (int mt = 0; mt < 4; mt++) {
                uint32_t ra = sb + (wm * 64 + mt * 16 + (lane & 15)) * TSTRIDE
                            + ks * 32 + ((lane >> 4) << 4);
                ldsm4(ah[mt],  ra);
                ldsm4(alr[mt], ra + TILE_SM);
            }
            uint32_t bh4[4][4], bl4[4][4];
            #pragma unroll
            for (int nt2 = 0; nt2 < 4; nt2++) {
                uint32_t rb = sb + 2 * TILE_SM
                            + (wn * 64 + nt2 * 16 + ((lane & 7) + ((lane >> 4) << 3))) * TSTRIDE
                            + ks * 32 + (((lane >> 3) & 1) << 4);
                ldsm4(bh4[nt2], rb);
                ldsm4(bl4[nt2], rb + TILE_SM);
            }
            #pragma unroll
            for (int p = 0; p < 3; p++) {
                #pragma unroll
                for (int mt = 0; mt < 4; mt++)
                    #pragma unroll
                    for (int nt2 = 0; nt2 < 4; nt2++)
                        #pragma unroll
                        for (int nn = 0; nn < 2; nn++) {
                            float* c = acc[mt][nt2 * 2 + nn];
                            const uint32_t* a = (p == 2) ? alr[mt] : ah[mt];
                            const uint32_t* bb = (p == 1) ? bl4[nt2] : bh4[nt2];
                            mma_bf16(c, a, bb[2 * nn], bb[2 * nn + 1]);
                        }
            }
        }
        __syncthreads();
    }

    // epilogue
    const int grp = lane >> 2, tig = lane & 3;
    #pragma unroll
    for (int mt = 0; mt < 4; mt++) {
        #pragma unroll
        for (int half = 0; half < 2; half++) {
            const size_t row = orow + wm * 64 + mt * 16 + grp + half * 8;
            if (mode == MODE_SCORE) {
                // exp + split write + deterministic partial row sum
                float rsum = 0.f;
                #pragma unroll
                for (int nt = 0; nt < 8; nt++) {
                    const int col = n0 + wn * 64 + nt * 8 + tig * 2;
                    float p0 = 0.f, p1 = 0.f;
                    if (col >= 1 && col < first) {
                        p0 = __expf(acc[mt][nt][half * 2 + 0] * INV_SQRT_DK);
                        rsum += p0;
                    }
                    if (col + 1 >= 1 && col + 1 < first) {
                        p1 = __expf(acc[mt][nt][half * 2 + 1] * INV_SQRT_DK);
                        rsum += p1;
                    }
                    __nv_bfloat16 h0, l0, h1, l1;
                    split2(p0, h0, l0); split2(p1, h1, l1);
                    *(uint32_t*)&oHi[row * ldo + col] = packbf(h0, h1);
                    *(uint32_t*)&oLo[row * ldo + col] = packbf(l0, l1);
                }
                rsum += __shfl_xor_sync(0xffffffff, rsum, 1);
                rsum += __shfl_xor_sync(0xffffffff, rsum, 2);
                if (tig == 0)
                    g_partial[row * 32 + (size_t)blockIdx.x * 2 + wn] = rsum;
            } else if (outF) {   // PV: fold partials -> inv_l, then scaled write
                const float* pp = &g_partial[row * 32];
                const int np = 2 * ((first + 127) >> 7);
                float s = 0.f;
                for (int i2 = tig; i2 < np; i2 += 4) s += pp[i2];
                s += __shfl_xor_sync(0xffffffff, s, 1);
                s += __shfl_xor_sync(0xffffffff, s, 2);
                const float rsc = 1.0f / fmaxf(s, 1e-30f);
                #pragma unroll
                for (int nt = 0; nt < 8; nt++) {
                    const int col = n0 + wn * 64 + nt * 8 + tig * 2;
                    *(float2*)&outF[row * ldo + col] =
                        make_float2(acc[mt][nt][half * 2 + 0] * rsc,
                                    acc[mt][nt][half * 2 + 1] * rsc);
                }
            } else {             // projections
                #pragma unroll
                for (int nt = 0; nt < 8; nt++) {
                    const int col = n0 + wn * 64 + nt * 8 + tig * 2;
                    float v0 = acc[mt][nt][half * 2 + 0];
                    float v1 = acc[mt][nt][half * 2 + 1];
                    if (addb) { v0 += bias[col]; v1 += bias[col + 1]; }
                    __nv_bfloat16 h0, l0, h1, l1;
                    split2(v0, h0, l0); split2(v1, h1, l1);
                    *(uint32_t*)&oHi[row * ldo + col] = packbf(h0, h1);
                    *(uint32_t*)&oLo[row * ldo + col] = packbf(l0, l1);
                }
            }
        }
    }
}

// ---------------- kernel: V projection (SIMT fp32), transposed split output --
__global__ __launch_bounds__(256) void v_gemm(
    const float* __restrict__ X, const float* __restrict__ W,
    const float* __restrict__ bias, const int* __restrict__ seq)
{
    const int tid = threadIdx.x;
    const int tx = tid & 15;
    const int ty = tid >> 4;

    const int b    = blockIdx.y >> 4;
    const int tloc = (blockIdx.y & 15) << 7;
    const int col0 = blockIdx.x << 7;
    const int first = seq_first(seq, b);
    if (tloc >= first) return;

    const int xrow0 = b * SS + tloc;

    __shared__ float As[16][128];
    __shared__ float Bs[16][128];

    float acc[8][8];
    #pragma unroll
    for (int i = 0; i < 8; i++)
        #pragma unroll
        for (int j = 0; j < 8; j++) acc[i][j] = 0.f;

    for (int k0 = 0; k0 < EE; k0 += 16) {
        #pragma unroll
        for (int v = tid; v < 512; v += 256) {
            int r = v >> 2;
            int c = (v & 3) << 2;
            float4 a = *(const float4*)&X[(size_t)(xrow0 + r) * EE + k0 + c];
            As[c + 0][r] = a.x; As[c + 1][r] = a.y;
            As[c + 2][r] = a.z; As[c + 3][r] = a.w;
            float4 wv = *(const float4*)&W[(size_t)(col0 + r) * EE + k0 + c];
            Bs[c + 0][r] = wv.x; Bs[c + 1][r] = wv.y;
            Bs[c + 2][r] = wv.z; Bs[c + 3][r] = wv.w;
        }
        __syncthreads();

        #pragma unroll
        for (int kk = 0; kk < 16; kk++) {
            float4 a0 = *(const float4*)&As[kk][ty * 8];
            float4 a1 = *(const float4*)&As[kk][ty * 8 + 4];
            float4 b0 = *(const float4*)&Bs[kk][tx * 8];
            float4 b1 = *(const float4*)&Bs[kk][tx * 8 + 4];
            float av[8] = {a0.x, a0.y, a0.z, a0.w, a1.x, a1.y, a1.z, a1.w};
            float bv[8] = {b0.x, b0.y, b0.z, b0.w, b1.x, b1.y, b1.z, b1.w};
            #pragma unroll
            for (int i = 0; i < 8; i++)
                #pragma unroll
                for (int j = 0; j < 8; j++)
                    acc[i][j] = fmaf(av[i], bv[j], acc[i][j]);
        }
        __syncthreads();
    }

    const int tok0 = tloc + ty * 8;
    #pragma unroll
    for (int j = 0; j < 8; j++) {
        const int e = col0 + tx * 8 + j;
        const float be = bias[e];
        uint32_t hu[4], lu[4];
        #pragma unroll
        for (int pr = 0; pr < 4; pr++) {
            __nv_bfloat16 h0, l0, h1, l1;
            split2(acc[pr * 2 + 0][j] + be, h0, l0);
            split2(acc[pr * 2 + 1][j] + be, h1, l1);
            hu[pr] = packbf(h0, h1);
            lu[pr] = packbf(l0, l1);
        }
        const size_t off = ((size_t)b * EE + e) * JMAX + tok0;
        *(uint4*)&g_Vth[off] = make_uint4(hu[0], hu[1], hu[2], hu[3]);
        *(uint4*)&g_Vtl[off] = make_uint4(lu[0], lu[1], lu[2], lu[3]);
    }
}

// ---------------------------------------------------------------------------
extern "C" void kernel_launch(void* const* d_in, const int* in_sizes, int n_in,
                              void* d_out, int out_size)
{
    const float* ebd = (const float*)d_in[0];
    const int*   seq = (const int*)d_in[1];
    const float* Wq = (const float*)d_in[2];
    const float* bq = (const float*)d_in[3];
    const float* Wk = (const float*)d_in[4];
    const float* bk = (const float*)d_in[5];
    const float* Wv = (const float*)d_in[6];
    const float* bv = (const float*)d_in[7];
    float* H = (float*)d_out;

    static cudaStream_t s2 = nullptr;
    static cudaEvent_t evFork = nullptr, evSplit = nullptr, evJoin = nullptr;
    if (!s2) {
        cudaFuncSetAttribute(tc_gemm, cudaFuncAttributeMaxDynamicSharedMemorySize, SMEM_TC);
        cudaStreamCreateWithFlags(&s2, cudaStreamNonBlocking);
        cudaEventCreateWithFlags(&evFork, cudaEventDisableTiming);
        cudaEventCreateWithFlags(&evSplit, cudaEventDisableTiming);
        cudaEventCreateWithFlags(&evJoin, cudaEventDisableTiming);
    }

    // fork: v_gemm (no deps) on side stream
    cudaEventRecord(evFork, 0);
    cudaStreamWaitEvent(s2, evFork, 0);
    v_gemm<<<dim3(EE / 128, BB * (JMAX / 128)), 256, 0, s2>>>(ebd, Wv, bv, seq);

    // 0) fp32 -> split bf16 for X, Wq, Wk (main stream)
    {
        size_t n4 = NX / 4;
        split_sel<<<(unsigned)((n4 + 255) / 256), 256>>>(ebd, 0, n4);
        size_t w4 = (size_t)EE * EE / 4;
        split_sel<<<(unsigned)((w4 + 255) / 256), 256>>>(Wq, 1, w4);
        split_sel<<<(unsigned)((w4 + 255) / 256), 256>>>(Wk, 2, w4);
    }
    cudaEventRecord(evSplit, 0);

    // PROJK on side stream (after splits + v_gemm), PROJQ on main — overlap
    cudaStreamWaitEvent(s2, evSplit, 0);
    tc_gemm<<<dim3(EE / 128, BB * (JMAX / 128), 1), 128, SMEM_TC, s2>>>(MODE_PROJK, seq, bk, nullptr);
    cudaEventRecord(evJoin, s2);

    tc_gemm<<<dim3(EE / 128, BB * SS / 128, 1), 128, SMEM_TC>>>(MODE_PROJQ, seq, bq, nullptr);

    // join: SCORE needs K (and PV later needs V, ordered before PROJK on s2)
    cudaStreamWaitEvent(0, evJoin, 0);

    // 2) scores -> exp splits + deterministic partial sums (no fp32 P)
    tc_gemm<<<dim3(JMAX / 128, SS / 128, BB), 128, SMEM_TC>>>(MODE_SCORE, seq, nullptr, nullptr);

    // 3) H = (P @ V) * inv_l, inv_l folded in epilogue (no row_sums kernel)
    tc_gemm<<<dim3(EE / 128, SS / 128, BB), 128, SMEM_TC>>>(MODE_PV, seq, nullptr, H);
}

// round 15
// speedup vs baseline: 1.0111x; 1.0077x over previous
#include <cuda_runtime.h>
#include <cuda_bf16.h>
#include <cstdint>

#define BB 8
#define SS 4096
#define EE 768
#define JMAX 2048
#define INV_SQRT_DK 0.03608439182435161f

#define NX ((size_t)BB * SS * EE)     // 25.2M
#define NK ((size_t)BB * JMAX * EE)   // 12.6M
#define NP ((size_t)BB * SS * JMAX)   // 67.1M

// ---------------- scratch (device globals; no allocations allowed) ----------
__device__ __nv_bfloat16 g_Xhi[NX], g_Xlo[NX];
__device__ __nv_bfloat16 g_Wqh[EE * EE], g_Wql[EE * EE];
__device__ __nv_bfloat16 g_Wkh[EE * EE], g_Wkl[EE * EE];
__device__ __nv_bfloat16 g_Qhi[NX], g_Qlo[NX];
__device__ __nv_bfloat16 g_Khi[NK], g_Klo[NK];
__device__ __nv_bfloat16 g_Vth[NK], g_Vtl[NK];   // [b][e][token] transposed V splits
__device__ __nv_bfloat16 g_Phi[NP], g_Plo[NP];   // unnormalized exp splits
__device__ float g_partial[(size_t)BB * SS * 32]; // per-(row, ctile, wn) sums
__device__ float g_invl[BB * SS];                 // per-row 1/sum

// ---------------- helpers ----------------------------------------------------
__device__ __forceinline__ uint32_t smem_to_u32(const void* p) {
    uint32_t a;
    asm("{ .reg .u64 t; cvta.to.shared.u64 t, %1; cvt.u32.u64 %0, t; }" : "=r"(a) : "l"(p));
    return a;
}
__device__ __forceinline__ int seq_first(const int* __restrict__ s, int b) {
    const bool is64 = (s[1] == 0);
    int v = is64 ? s[4 * b] : s[2 * b];
    if (v < 1) v = 1;
    if (v > JMAX) v = JMAX;
    return v;
}
__device__ __forceinline__ void split2(float v, __nv_bfloat16& h, __nv_bfloat16& l) {
    h = __float2bfloat16(v);
    l = __float2bfloat16(v - __bfloat162float(h));
}
__device__ __forceinline__ uint32_t packbf(__nv_bfloat16 a, __nv_bfloat16 b) {
    return (uint32_t)__bfloat16_as_ushort(a) | ((uint32_t)__bfloat16_as_ushort(b) << 16);
}

__device__ __forceinline__ void ldsm4(uint32_t* d, uint32_t a) {
    asm volatile("ldmatrix.sync.aligned.m8n8.x4.shared.b16 {%0,%1,%2,%3}, [%4];"
                 : "=r"(d[0]), "=r"(d[1]), "=r"(d[2]), "=r"(d[3]) : "r"(a));
}
__device__ __forceinline__ void mma_bf16(float* c, const uint32_t* a, uint32_t b0, uint32_t b1) {
    asm volatile(
        "mma.sync.aligned.m16n8k16.row.col.f32.bf16.bf16.f32 "
        "{%0,%1,%2,%3}, {%4,%5,%6,%7}, {%8,%9}, {%0,%1,%2,%3};"
        : "+f"(c[0]), "+f"(c[1]), "+f"(c[2]), "+f"(c[3])
        : "r"(a[0]), "r"(a[1]), "r"(a[2]), "r"(a[3]), "r"(b0), "r"(b1));
}
#define CP_ASYNC16(sa, ga) \
    asm volatile("cp.async.cg.shared.global [%0], [%1], 16;" :: "r"(sa), "l"(ga) : "memory")
#define CP_COMMIT() asm volatile("cp.async.commit_group;" ::: "memory")
#define CP_WAIT(n)  asm volatile("cp.async.wait_group %0;" :: "n"(n) : "memory")

// ---------------- kernel: fp32 -> (hi, lo) bf16 splits ------------------------
__global__ __launch_bounds__(256) void split_sel(const float* __restrict__ src,
                                                 int sel, size_t n4)
{
    size_t i = (size_t)blockIdx.x * 256 + threadIdx.x;
    if (i >= n4) return;
    __nv_bfloat16 *dh, *dl;
    if (sel == 0)      { dh = g_Xhi; dl = g_Xlo; }
    else if (sel == 1) { dh = g_Wqh; dl = g_Wql; }
    else               { dh = g_Wkh; dl = g_Wkl; }
    float4 v = ((const float4*)src)[i];
    __nv_bfloat16 h0, l0, h1, l1, h2, l2, h3, l3;
    split2(v.x, h0, l0); split2(v.y, h1, l1);
    split2(v.z, h2, l2); split2(v.w, h3, l3);
    ((uint2*)dh)[i] = make_uint2(packbf(h0, h1), packbf(h2, h3));
    ((uint2*)dl)[i] = make_uint2(packbf(l0, l1), packbf(l2, l3));
}

// ---------------- generic split-bf16 NT GEMM on mma.sync ---------------------
#define TSTRIDE 80
#define TILE_SM (128 * TSTRIDE)          // 10240
#define STAGE_SM (4 * TILE_SM)           // 40960
#define SMEM_TC (2 * STAGE_SM)           // 81920

#define MODE_PROJQ 0
#define MODE_PROJK 1
#define MODE_SCORE 2
#define MODE_PV    3

__global__ __launch_bounds__(128, 2) void tc_gemm(int mode, const int* __restrict__ seq,
                                                  const float* __restrict__ bias,
                                                  float* __restrict__ Hout)
{
    const int n0 = blockIdx.x << 7;
    int b = 0, first = 0, Kdim = EE;
    size_t arow, brow, orow;
    int lda, ldb, ldo = EE;
    const __nv_bfloat16 *Ah, *Al, *Bh, *Bl;
    float* outF = nullptr;
    __nv_bfloat16 *oHi = nullptr, *oLo = nullptr;
    bool addb = false;

    if (mode == MODE_PROJQ) {
        arow = (size_t)blockIdx.y << 7; brow = n0; orow = arow;
        Ah = g_Xhi; Al = g_Xlo; lda = EE; Bh = g_Wqh; Bl = g_Wql; ldb = EE;
        oHi = g_Qhi; oLo = g_Qlo; ldo = EE; addb = true;
    } else if (mode == MODE_PROJK) {
        b = blockIdx.y >> 4;
        int tloc = (blockIdx.y & 15) << 7;
        first = seq_first(seq, b);
        if (tloc >= first) return;
        arow = (size_t)b * SS + tloc; brow = n0; orow = (size_t)b * JMAX + tloc;
        Ah = g_Xhi; Al = g_Xlo; lda = EE; Bh = g_Wkh; Bl = g_Wkl; ldb = EE;
        oHi = g_Khi; oLo = g_Klo; ldo = EE; addb = true;
    } else if (mode == MODE_SCORE) {
        b = blockIdx.z; first = seq_first(seq, b);
        if (n0 >= first) return;
        arow = (size_t)b * SS + ((size_t)blockIdx.y << 7);
        brow = (size_t)b * JMAX + n0;
        Ah = g_Qhi; Al = g_Qlo; lda = EE; Bh = g_Khi; Bl = g_Klo; ldb = EE;
        oHi = g_Phi; oLo = g_Plo; ldo = JMAX; orow = arow;
    } else { // MODE_PV
        b = blockIdx.z; first = seq_first(seq, b);
        Kdim = (first + 63) & ~63;
        arow = (size_t)b * SS + ((size_t)blockIdx.y << 7);
        brow = (size_t)b * EE + n0;
        Ah = g_Phi; Al = g_Plo; lda = JMAX; Bh = g_Vth; Bl = g_Vtl; ldb = JMAX;
        outF = Hout; ldo = EE; orow = arow;
    }

    extern __shared__ char smem[];
    const uint32_t sbase = smem_to_u32(smem);
    const int tid  = threadIdx.x;
    const int lane = tid & 31, wid = tid >> 5;
    const int wm = wid >> 1, wn = wid & 1;          // 2 x 2 warp grid, warp tile 64x64

    const char* gsrc[4] = { (const char*)(Ah + arow * lda), (const char*)(Al + arow * lda),
                            (const char*)(Bh + brow * ldb), (const char*)(Bl + brow * ldb) };
    const size_t ldby[4] = { (size_t)lda * 2, (size_t)lda * 2,
                             (size_t)ldb * 2, (size_t)ldb * 2 };

    auto load_stage = [&](int s, int ki) {
        const size_t k0b = (size_t)ki * 64;          // 32 bf16 = 64 bytes
        const uint32_t sb = sbase + s * STAGE_SM;
        #pragma unroll
        for (int j = 0; j < 16; j++) {
            int t = tid + j * 128;                   // 2048 chunks of 16B
            int tile = t >> 9, row = (t >> 2) & 127, c = t & 3;
            uint32_t sa = sb + tile * TILE_SM + row * TSTRIDE + c * 16;
            const char* ga = gsrc[tile] + (size_t)row * ldby[tile] + k0b + c * 16;
            CP_ASYNC16(sa, ga);
        }
    };

    float acc[4][8][4];
    #pragma unroll
    for (int mt = 0; mt < 4; mt++)
        #pragma unroll
        for (int nt = 0; nt < 8; nt++)
            #pragma unroll
            for (int r = 0; r < 4; r++) acc[mt][nt][r] = 0.f;

    const int kt = Kdim >> 5;                        // BK = 32

    load_stage(0, 0);
    CP_COMMIT();

    for (int i = 0; i < kt; i++) {
        const int cur = i & 1;
        if (i + 1 < kt) { load_stage(cur ^ 1, i + 1); CP_COMMIT(); CP_WAIT(1); }
        else            { CP_WAIT(0); }
        __syncthreads();

        const uint32_t sb = sbase + cur * STAGE_SM;
        #pragma unroll
        for (int ks = 0; ks < 2; ks++) {             // two k16 halves of BK=32
            uint32_t ah[4][4], alr[4][4];
            #pragma unroll
            for (int mt = 0; mt < 4; mt++) {
                uint32_t ra = sb + (wm * 64 + mt * 16 + (lane & 15)) * TSTRIDE
                            + ks * 32 + ((lane >> 4) << 4);
                ldsm4(ah[mt],  ra);
                ldsm4(alr[mt], ra + TILE_SM);
            }
            uint32_t bh4[4][4], bl4[4][4];
            #pragma unroll
            for (int nt2 = 0; nt2 < 4; nt2++) {
                uint32_t rb = sb + 2 * TILE_SM
                            + (wn * 64 + nt2 * 16 + ((lane & 7) + ((lane >> 4) << 3))) * TSTRIDE
                            + ks * 32 + (((lane >> 3) & 1) << 4);
                ldsm4(bh4[nt2], rb);
                ldsm4(bl4[nt2], rb + TILE_SM);
            }
            #pragma unroll
            for (int p = 0; p < 3; p++) {
                #pragma unroll
                for (int mt = 0; mt < 4; mt++)
                    #pragma unroll
                    for (int nt2 = 0; nt2 < 4; nt2++)
                        #pragma unroll
                        for (int nn = 0; nn < 2; nn++) {
                            float* c = acc[mt][nt2 * 2 + nn];
                            const uint32_t* a = (p == 2) ? alr[mt] : ah[mt];
                            const uint32_t* bb = (p == 1) ? bl4[nt2] : bh4[nt2];
                            mma_bf16(c, a, bb[2 * nn], bb[2 * nn + 1]);
                        }
            }
        }
        __syncthreads();
    }

    // epilogue
    const int grp = lane >> 2, tig = lane & 3;
    #pragma unroll
    for (int mt = 0; mt < 4; mt++) {
        #pragma unroll
        for (int half = 0; half < 2; half++) {
            const size_t row = orow + wm * 64 + mt * 16 + grp + half * 8;
            if (mode == MODE_SCORE) {
                // exp + split write + deterministic partial row sum
                float rsum = 0.f;
                #pragma unroll
                for (int nt = 0; nt < 8; nt++) {
                    const int col = n0 + wn * 64 + nt * 8 + tig * 2;
                    float p0 = 0.f, p1 = 0.f;
                    if (col >= 1 && col < first) {
                        p0 = __expf(acc[mt][nt][half * 2 + 0] * INV_SQRT_DK);
                        rsum += p0;
                    }
                    if (col + 1 >= 1 && col + 1 < first) {
                        p1 = __expf(acc[mt][nt][half * 2 + 1] * INV_SQRT_DK);
                        rsum += p1;
                    }
                    __nv_bfloat16 h0, l0, h1, l1;
                    split2(p0, h0, l0); split2(p1, h1, l1);
                    *(uint32_t*)&oHi[row * ldo + col] = packbf(h0, h1);
                    *(uint32_t*)&oLo[row * ldo + col] = packbf(l0, l1);
                }
                rsum += __shfl_xor_sync(0xffffffff, rsum, 1);
                rsum += __shfl_xor_sync(0xffffffff, rsum, 2);
                if (tig == 0)
                    g_partial[row * 32 + (size_t)blockIdx.x * 2 + wn] = rsum;
            } else if (outF) {   // PV
                const float rsc = g_invl[row];
                #pragma unroll
                for (int nt = 0; nt < 8; nt++) {
                    const int col = n0 + wn * 64 + nt * 8 + tig * 2;
                    *(float2*)&outF[row * ldo + col] =
                        make_float2(acc[mt][nt][half * 2 + 0] * rsc,
                                    acc[mt][nt][half * 2 + 1] * rsc);
                }
            } else {             // projections
                #pragma unroll
                for (int nt = 0; nt < 8; nt++) {
                    const int col = n0 + wn * 64 + nt * 8 + tig * 2;
                    float v0 = acc[mt][nt][half * 2 + 0];
                    float v1 = acc[mt][nt][half * 2 + 1];
                    if (addb) { v0 += bias[col]; v1 += bias[col + 1]; }
                    __nv_bfloat16 h0, l0, h1, l1;
                    split2(v0, h0, l0); split2(v1, h1, l1);
                    *(uint32_t*)&oHi[row * ldo + col] = packbf(h0, h1);
                    *(uint32_t*)&oLo[row * ldo + col] = packbf(l0, l1);
                }
            }
        }
    }
}

// ---------------- kernel: fold partial sums -> inv_l -------------------------
__global__ __launch_bounds__(256) void row_sums(const int* __restrict__ seq)
{
    const int row = blockIdx.x * 256 + threadIdx.x;
    if (row >= BB * SS) return;
    const int b = row >> 12;
    const int first = seq_first(seq, b);
    const int np = 2 * ((first + 127) >> 7);       // partials written for this row
    const float* p = &g_partial[(size_t)row * 32];
    float s = 0.f;
    for (int i = 0; i < np; i++) s += p[i];
    g_invl[row] = 1.0f / fmaxf(s, 1e-30f);
}

// ---------------- kernel: V projection (SIMT fp32), transposed split output --
__global__ __launch_bounds__(256) void v_gemm(
    const float* __restrict__ X, const float* __restrict__ W,
    const float* __restrict__ bias, const int* __restrict__ seq)
{
    const int tid = threadIdx.x;
    const int tx = tid & 15;
    const int ty = tid >> 4;

    const int b    = blockIdx.y >> 4;
    const int tloc = (blockIdx.y & 15) << 7;
    const int col0 = blockIdx.x << 7;
    const int first = seq_first(seq, b);
    if (tloc >= first) return;

    const int xrow0 = b * SS + tloc;

    __shared__ float As[16][128];
    __shared__ float Bs[16][128];

    float acc[8][8];
    #pragma unroll
    for (int i = 0; i < 8; i++)
        #pragma unroll
        for (int j = 0; j < 8; j++) acc[i][j] = 0.f;

    for (int k0 = 0; k0 < EE; k0 += 16) {
        #pragma unroll
        for (int v = tid; v < 512; v += 256) {
            int r = v >> 2;
            int c = (v & 3) << 2;
            float4 a = *(const float4*)&X[(size_t)(xrow0 + r) * EE + k0 + c];
            As[c + 0][r] = a.x; As[c + 1][r] = a.y;
            As[c + 2][r] = a.z; As[c + 3][r] = a.w;
            float4 wv = *(const float4*)&W[(size_t)(col0 + r) * EE + k0 + c];
            Bs[c + 0][r] = wv.x; Bs[c + 1][r] = wv.y;
            Bs[c + 2][r] = wv.z; Bs[c + 3][r] = wv.w;
        }
        __syncthreads();

        #pragma unroll
        for (int kk = 0; kk < 16; kk++) {
            float4 a0 = *(const float4*)&As[kk][ty * 8];
            float4 a1 = *(const float4*)&As[kk][ty * 8 + 4];
            float4 b0 = *(const float4*)&Bs[kk][tx * 8];
            float4 b1 = *(const float4*)&Bs[kk][tx * 8 + 4];
            float av[8] = {a0.x, a0.y, a0.z, a0.w, a1.x, a1.y, a1.z, a1.w};
            float bv[8] = {b0.x, b0.y, b0.z, b0.w, b1.x, b1.y, b1.z, b1.w};
            #pragma unroll
            for (int i = 0; i < 8; i++)
                #pragma unroll
                for (int j = 0; j < 8; j++)
                    acc[i][j] = fmaf(av[i], bv[j], acc[i][j]);
        }
        __syncthreads();
    }

    const int tok0 = tloc + ty * 8;
    #pragma unroll
    for (int j = 0; j < 8; j++) {
        const int e = col0 + tx * 8 + j;
        const float be = bias[e];
        uint32_t hu[4], lu[4];
        #pragma unroll
        for (int pr = 0; pr < 4; pr++) {
            __nv_bfloat16 h0, l0, h1, l1;
            split2(acc[pr * 2 + 0][j] + be, h0, l0);
            split2(acc[pr * 2 + 1][j] + be, h1, l1);
            hu[pr] = packbf(h0, h1);
            lu[pr] = packbf(l0, l1);
        }
        const size_t off = ((size_t)b * EE + e) * JMAX + tok0;
        *(uint4*)&g_Vth[off] = make_uint4(hu[0], hu[1], hu[2], hu[3]);
        *(uint4*)&g_Vtl[off] = make_uint4(lu[0], lu[1], lu[2], lu[3]);
    }
}

// ---------------------------------------------------------------------------
extern "C" void kernel_launch(void* const* d_in, const int* in_sizes, int n_in,
                              void* d_out, int out_size)
{
    const float* ebd = (const float*)d_in[0];
    const int*   seq = (const int*)d_in[1];
    const float* Wq = (const float*)d_in[2];
    const float* bq = (const float*)d_in[3];
    const float* Wk = (const float*)d_in[4];
    const float* bk = (const float*)d_in[5];
    const float* Wv = (const float*)d_in[6];
    const float* bv = (const float*)d_in[7];
    float* H = (float*)d_out;

    static cudaStream_t s2 = nullptr, s3 = nullptr;
    static cudaEvent_t evFork = nullptr, evSplit = nullptr, evK = nullptr, evV = nullptr;
    if (!s2) {
        cudaFuncSetAttribute(tc_gemm, cudaFuncAttributeMaxDynamicSharedMemorySize, SMEM_TC);
        cudaStreamCreateWithFlags(&s2, cudaStreamNonBlocking);
        cudaStreamCreateWithFlags(&s3, cudaStreamNonBlocking);
        cudaEventCreateWithFlags(&evFork, cudaEventDisableTiming);
        cudaEventCreateWithFlags(&evSplit, cudaEventDisableTiming);
        cudaEventCreateWithFlags(&evK, cudaEventDisableTiming);
        cudaEventCreateWithFlags(&evV, cudaEventDisableTiming);
    }

    // fork: v_gemm (no deps) on s3 — off the K critical path entirely
    cudaEventRecord(evFork, 0);
    cudaStreamWaitEvent(s3, evFork, 0);
    v_gemm<<<dim3(EE / 128, BB * (JMAX / 128)), 256, 0, s3>>>(ebd, Wv, bv, seq);
    cudaEventRecord(evV, s3);

    // 0) fp32 -> split bf16 for X, Wq, Wk (main stream)
    {
        size_t n4 = NX / 4;
        split_sel<<<(unsigned)((n4 + 255) / 256), 256>>>(ebd, 0, n4);
        size_t w4 = (size_t)EE * EE / 4;
        split_sel<<<(unsigned)((w4 + 255) / 256), 256>>>(Wq, 1, w4);
        split_sel<<<(unsigned)((w4 + 255) / 256), 256>>>(Wk, 2, w4);
    }
    cudaEventRecord(evSplit, 0);

    // PROJK on s2 (right after splits — no longer behind v_gemm), PROJQ on main
    cudaStreamWaitEvent(s2, evSplit, 0);
    tc_gemm<<<dim3(EE / 128, BB * (JMAX / 128), 1), 128, SMEM_TC, s2>>>(MODE_PROJK, seq, bk, nullptr);
    cudaEventRecord(evK, s2);

    tc_gemm<<<dim3(EE / 128, BB * SS / 128, 1), 128, SMEM_TC>>>(MODE_PROJQ, seq, bq, nullptr);

    // SCORE needs only K
    cudaStreamWaitEvent(0, evK, 0);

    // 2) scores -> exp splits + deterministic partial sums
    tc_gemm<<<dim3(JMAX / 128, SS / 128, BB), 128, SMEM_TC>>>(MODE_SCORE, seq, nullptr, nullptr);

    // 3) fold partials -> inv_l
    row_sums<<<(BB * SS + 255) / 256, 256>>>(seq);

    // PV needs V (v_gemm finished long ago, hidden under PROJQ/SCORE)
    cudaStreamWaitEvent(0, evV, 0);

    // 4) H = (P @ V) * inv_l
    tc_gemm<<<dim3(EE / 128, SS / 128, BB), 128, SMEM_TC>>>(MODE_PV, seq, nullptr, H);
}

// round 16
// speedup vs baseline: 1.1510x; 1.1384x over previous
#include <cuda_runtime.h>
#include <cuda_bf16.h>
#include <cstdint>

#define BB 8
#define SS 4096
#define EE 768
#define JMAX 2048
#define INV_SQRT_DK 0.03608439182435161f

#define NX ((size_t)BB * SS * EE)     // 25.2M
#define NK ((size_t)BB * JMAX * EE)   // 12.6M
#define NP ((size_t)BB * SS * JMAX)   // 67.1M

// ---------------- scratch (device globals; no allocations allowed) ----------
__device__ __nv_bfloat16 g_Xhi[NX], g_Xlo[NX];
__device__ __nv_bfloat16 g_Wqh[EE * EE], g_Wql[EE * EE];
__device__ __nv_bfloat16 g_Wkh[EE * EE], g_Wkl[EE * EE];
__device__ __nv_bfloat16 g_Wvh[EE * EE], g_Wvl[EE * EE];
__device__ __nv_bfloat16 g_Qhi[NX], g_Qlo[NX];
__device__ __nv_bfloat16 g_Khi[NK], g_Klo[NK];
__device__ __nv_bfloat16 g_Vth[NK], g_Vtl[NK];   // [b][e][token] transposed V splits
__device__ __nv_bfloat16 g_Phi[NP], g_Plo[NP];   // unnormalized exp splits
__device__ float g_partial[(size_t)BB * SS * 32]; // per-(row, ctile, wn) sums
__device__ float g_invl[BB * SS];                 // per-row 1/sum

// ---------------- helpers ----------------------------------------------------
__device__ __forceinline__ uint32_t smem_to_u32(const void* p) {
    uint32_t a;
    asm("{ .reg .u64 t; cvta.to.shared.u64 t, %1; cvt.u32.u64 %0, t; }" : "=r"(a) : "l"(p));
    return a;
}
__device__ __forceinline__ int seq_first(const int* __restrict__ s, int b) {
    const bool is64 = (s[1] == 0);
    int v = is64 ? s[4 * b] : s[2 * b];
    if (v < 1) v = 1;
    if (v > JMAX) v = JMAX;
    return v;
}
__device__ __forceinline__ void split2(float v, __nv_bfloat16& h, __nv_bfloat16& l) {
    h = __float2bfloat16(v);
    l = __float2bfloat16(v - __bfloat162float(h));
}
__device__ __forceinline__ uint32_t packbf(__nv_bfloat16 a, __nv_bfloat16 b) {
    return (uint32_t)__bfloat16_as_ushort(a) | ((uint32_t)__bfloat16_as_ushort(b) << 16);
}

__device__ __forceinline__ void ldsm4(uint32_t* d, uint32_t a) {
    asm volatile("ldmatrix.sync.aligned.m8n8.x4.shared.b16 {%0,%1,%2,%3}, [%4];"
                 : "=r"(d[0]), "=r"(d[1]), "=r"(d[2]), "=r"(d[3]) : "r"(a));
}
__device__ __forceinline__ void mma_bf16(float* c, const uint32_t* a, uint32_t b0, uint32_t b1) {
    asm volatile(
        "mma.sync.aligned.m16n8k16.row.col.f32.bf16.bf16.f32 "
        "{%0,%1,%2,%3}, {%4,%5,%6,%7}, {%8,%9}, {%0,%1,%2,%3};"
        : "+f"(c[0]), "+f"(c[1]), "+f"(c[2]), "+f"(c[3])
        : "r"(a[0]), "r"(a[1]), "r"(a[2]), "r"(a[3]), "r"(b0), "r"(b1));
}
#define CP_ASYNC16(sa, ga) \
    asm volatile("cp.async.cg.shared.global [%0], [%1], 16;" :: "r"(sa), "l"(ga) : "memory")
#define CP_COMMIT() asm volatile("cp.async.commit_group;" ::: "memory")
#define CP_WAIT(n)  asm volatile("cp.async.wait_group %0;" :: "n"(n) : "memory")

// ---------------- kernel: fp32 -> (hi, lo) bf16 splits ------------------------
__global__ __launch_bounds__(256) void split_sel(const float* __restrict__ src,
                                                 int sel, size_t n4)
{
    size_t i = (size_t)blockIdx.x * 256 + threadIdx.x;
    if (i >= n4) return;
    __nv_bfloat16 *dh, *dl;
    if (sel == 0)      { dh = g_Xhi; dl = g_Xlo; }
    else if (sel == 1) { dh = g_Wqh; dl = g_Wql; }
    else if (sel == 2) { dh = g_Wkh; dl = g_Wkl; }
    else               { dh = g_Wvh; dl = g_Wvl; }
    float4 v = ((const float4*)src)[i];
    __nv_bfloat16 h0, l0, h1, l1, h2, l2, h3, l3;
    split2(v.x, h0, l0); split2(v.y, h1, l1);
    split2(v.z, h2, l2); split2(v.w, h3, l3);
    ((uint2*)dh)[i] = make_uint2(packbf(h0, h1), packbf(h2, h3));
    ((uint2*)dl)[i] = make_uint2(packbf(l0, l1), packbf(l2, l3));
}

// ---------------- generic split-bf16 NT GEMM on mma.sync ---------------------
#define TSTRIDE 80
#define TILE_SM (128 * TSTRIDE)          // 10240
#define STAGE_SM (4 * TILE_SM)           // 40960
#define SMEM_TC (2 * STAGE_SM)           // 81920

#define MODE_PROJQ 0
#define MODE_PROJK 1
#define MODE_SCORE 2
#define MODE_PV    3
#define MODE_PROJV 4

__global__ __launch_bounds__(128, 2) void tc_gemm(int mode, const int* __restrict__ seq,
                                                  const float* __restrict__ bias,
                                                  float* __restrict__ Hout)
{
    const int n0 = blockIdx.x << 7;
    int b = 0, first = 0, Kdim = EE;
    size_t arow, brow, orow;
    int lda, ldb, ldo = EE;
    const __nv_bfloat16 *Ah, *Al, *Bh, *Bl;
    float* outF = nullptr;
    __nv_bfloat16 *oHi = nullptr, *oLo = nullptr;
    bool addb = false;
    int tloc = 0;

    if (mode == MODE_PROJQ) {
        arow = (size_t)blockIdx.y << 7; brow = n0; orow = arow;
        Ah = g_Xhi; Al = g_Xlo; lda = EE; Bh = g_Wqh; Bl = g_Wql; ldb = EE;
        oHi = g_Qhi; oLo = g_Qlo; ldo = EE; addb = true;
    } else if (mode == MODE_PROJK || mode == MODE_PROJV) {
        b = blockIdx.y >> 4;
        tloc = (blockIdx.y & 15) << 7;
        first = seq_first(seq, b);
        if (tloc >= first) return;
        arow = (size_t)b * SS + tloc; brow = n0; orow = (size_t)b * JMAX + tloc;
        Ah = g_Xhi; Al = g_Xlo; lda = EE;
        if (mode == MODE_PROJK) { Bh = g_Wkh; Bl = g_Wkl; }
        else                    { Bh = g_Wvh; Bl = g_Wvl; }
        ldb = EE;
        oHi = g_Khi; oLo = g_Klo; ldo = EE; addb = true;  // unused for PROJV
    } else if (mode == MODE_SCORE) {
        b = blockIdx.z; first = seq_first(seq, b);
        if (n0 >= first) return;
        arow = (size_t)b * SS + ((size_t)blockIdx.y << 7);
        brow = (size_t)b * JMAX + n0;
        Ah = g_Qhi; Al = g_Qlo; lda = EE; Bh = g_Khi; Bl = g_Klo; ldb = EE;
        oHi = g_Phi; oLo = g_Plo; ldo = JMAX; orow = arow;
    } else { // MODE_PV
        b = blockIdx.z; first = seq_first(seq, b);
        Kdim = (first + 63) & ~63;
        arow = (size_t)b * SS + ((size_t)blockIdx.y << 7);
        brow = (size_t)b * EE + n0;
        Ah = g_Phi; Al = g_Plo; lda = JMAX; Bh = g_Vth; Bl = g_Vtl; ldb = JMAX;
        outF = Hout; ldo = EE; orow = arow;
    }

    extern __shared__ char smem[];
    const uint32_t sbase = smem_to_u32(smem);
    const int tid  = threadIdx.x;
    const int lane = tid & 31, wid = tid >> 5;
    const int wm = wid >> 1, wn = wid & 1;          // 2 x 2 warp grid, warp tile 64x64

    const char* gsrc[4] = { (const char*)(Ah + arow * lda), (const char*)(Al + arow * lda),
                            (const char*)(Bh + brow * ldb), (const char*)(Bl + brow * ldb) };
    const size_t ldby[4] = { (size_t)lda * 2, (size_t)lda * 2,
                             (size_t)ldb * 2, (size_t)ldb * 2 };

    auto load_stage = [&](int s, int ki) {
        const size_t k0b = (size_t)ki * 64;          // 32 bf16 = 64 bytes
        const uint32_t sb = sbase + s * STAGE_SM;
        #pragma unroll
        for (int j = 0; j < 16; j++) {
            int t = tid + j * 128;                   // 2048 chunks of 16B
            int tile = t >> 9, row = (t >> 2) & 127, c = t & 3;
            uint32_t sa = sb + tile * TILE_SM + row * TSTRIDE + c * 16;
            const char* ga = gsrc[tile] + (size_t)row * ldby[tile] + k0b + c * 16;
            CP_ASYNC16(sa, ga);
        }
    };

    float acc[4][8][4];
    #pragma unroll
    for (int mt = 0; mt < 4; mt++)
        #pragma unroll
        for (int nt = 0; nt < 8; nt++)
            #pragma unroll
            for (int r = 0; r < 4; r++) acc[mt][nt][r] = 0.f;

    const int kt = Kdim >> 5;                        // BK = 32

    load_stage(0, 0);
    CP_COMMIT();

    for (int i = 0; i < kt; i++) {
        const int cur = i & 1;
        if (i + 1 < kt) { load_stage(cur ^ 1, i + 1); CP_COMMIT(); CP_WAIT(1); }
        else            { CP_WAIT(0); }
        __syncthreads();

        const uint32_t sb = sbase + cur * STAGE_SM;
        #pragma unroll
        for (int ks = 0; ks < 2; ks++) {             // two k16 halves of BK=32
            uint32_t ah[4][4], alr[4][4];
            #pragma unroll
            for (int mt = 0; mt < 4; mt++) {
                uint32_t ra = sb + (wm * 64 + mt * 16 + (lane & 15)) * TSTRIDE
                            + ks * 32 + ((lane >> 4) << 4);
                ldsm4(ah[mt],  ra);
                ldsm4(alr[mt], ra + TILE_SM);
            }
            uint32_t bh4[4][4], bl4[4][4];
            #pragma unroll
            for (int nt2 = 0; nt2 < 4; nt2++) {
                uint32_t rb = sb + 2 * TILE_SM
                            + (wn * 64 + nt2 * 16 + ((lane & 7) + ((lane >> 4) << 3))) * TSTRIDE
                            + ks * 32 + (((lane >> 3) & 1) << 4);
                ldsm4(bh4[nt2], rb);
                ldsm4(bl4[nt2], rb + TILE_SM);
            }
            #pragma unroll
            for (int p = 0; p < 3; p++) {
                #pragma unroll
                for (int mt = 0; mt < 4; mt++)
                    #pragma unroll
                    for (int nt2 = 0; nt2 < 4; nt2++)
                        #pragma unroll
                        for (int nn = 0; nn < 2; nn++) {
                            float* c = acc[mt][nt2 * 2 + nn];
                            const uint32_t* a = (p == 2) ? alr[mt] : ah[mt];
                            const uint32_t* bb = (p == 1) ? bl4[nt2] : bh4[nt2];
                            mma_bf16(c, a, bb[2 * nn], bb[2 * nn + 1]);
                        }
            }
        }
        __syncthreads();
    }

    // epilogue
    const int grp = lane >> 2, tig = lane & 3;
    #pragma unroll
    for (int mt = 0; mt < 4; mt++) {
        #pragma unroll
        for (int half = 0; half < 2; half++) {
            const size_t row = orow + wm * 64 + mt * 16 + grp + half * 8;
            if (mode == MODE_SCORE) {
                // exp + split write + deterministic partial row sum
                float rsum = 0.f;
                #pragma unroll
                for (int nt = 0; nt < 8; nt++) {
                    const int col = n0 + wn * 64 + nt * 8 + tig * 2;
                    float p0 = 0.f, p1 = 0.f;
                    if (col >= 1 && col < first) {
                        p0 = __expf(acc[mt][nt][half * 2 + 0] * INV_SQRT_DK);
                        rsum += p0;
                    }
                    if (col + 1 >= 1 && col + 1 < first) {
                        p1 = __expf(acc[mt][nt][half * 2 + 1] * INV_SQRT_DK);
                        rsum += p1;
                    }
                    __nv_bfloat16 h0, l0, h1, l1;
                    split2(p0, h0, l0); split2(p1, h1, l1);
                    *(uint32_t*)&oHi[row * ldo + col] = packbf(h0, h1);
                    *(uint32_t*)&oLo[row * ldo + col] = packbf(l0, l1);
                }
                rsum += __shfl_xor_sync(0xffffffff, rsum, 1);
                rsum += __shfl_xor_sync(0xffffffff, rsum, 2);
                if (tig == 0)
                    g_partial[row * 32 + (size_t)blockIdx.x * 2 + wn] = rsum;
            } else if (mode == MODE_PROJV) {
                // transposed split write: Vt[b][e][token]
                const int tok = tloc + wm * 64 + mt * 16 + grp + half * 8;
                __nv_bfloat16* vh = g_Vth + (size_t)b * EE * JMAX;
                __nv_bfloat16* vl = g_Vtl + (size_t)b * EE * JMAX;
                #pragma unroll
                for (int nt = 0; nt < 8; nt++) {
                    const int col = n0 + wn * 64 + nt * 8 + tig * 2;
                    float v0 = acc[mt][nt][half * 2 + 0] + bias[col];
                    float v1 = acc[mt][nt][half * 2 + 1] + bias[col + 1];
                    __nv_bfloat16 h0, l0, h1, l1;
                    split2(v0, h0, l0); split2(v1, h1, l1);
                    vh[(size_t)col * JMAX + tok]       = h0;
                    vh[(size_t)(col + 1) * JMAX + tok] = h1;
                    vl[(size_t)col * JMAX + tok]       = l0;
                    vl[(size_t)(col + 1) * JMAX + tok] = l1;
                }
            } else if (outF) {   // PV
                const float rsc = g_invl[row];
                #pragma unroll
                for (int nt = 0; nt < 8; nt++) {
                    const int col = n0 + wn * 64 + nt * 8 + tig * 2;
                    *(float2*)&outF[row * ldo + col] =
                        make_float2(acc[mt][nt][half * 2 + 0] * rsc,
                                    acc[mt][nt][half * 2 + 1] * rsc);
                }
            } else {             // PROJQ / PROJK
                #pragma unroll
                for (int nt = 0; nt < 8; nt++) {
                    const int col = n0 + wn * 64 + nt * 8 + tig * 2;
                    float v0 = acc[mt][nt][half * 2 + 0];
                    float v1 = acc[mt][nt][half * 2 + 1];
                    if (addb) { v0 += bias[col]; v1 += bias[col + 1]; }
                    __nv_bfloat16 h0, l0, h1, l1;
                    split2(v0, h0, l0); split2(v1, h1, l1);
                    *(uint32_t*)&oHi[row * ldo + col] = packbf(h0, h1);
                    *(uint32_t*)&oLo[row * ldo + col] = packbf(l0, l1);
                }
            }
        }
    }
}

// ---------------- kernel: fold partial sums -> inv_l -------------------------
__global__ __launch_bounds__(256) void row_sums(const int* __restrict__ seq)
{
    const int row = blockIdx.x * 256 + threadIdx.x;
    if (row >= BB * SS) return;
    const int b = row >> 12;
    const int first = seq_first(seq, b);
    const int np = 2 * ((first + 127) >> 7);       // partials written for this row
    const float* p = &g_partial[(size_t)row * 32];
    float s = 0.f;
    for (int i = 0; i < np; i++) s += p[i];
    g_invl[row] = 1.0f / fmaxf(s, 1e-30f);
}

// ---------------------------------------------------------------------------
extern "C" void kernel_launch(void* const* d_in, const int* in_sizes, int n_in,
                              void* d_out, int out_size)
{
    const float* ebd = (const float*)d_in[0];
    const int*   seq = (const int*)d_in[1];
    const float* Wq = (const float*)d_in[2];
    const float* bq = (const float*)d_in[3];
    const float* Wk = (const float*)d_in[4];
    const float* bk = (const float*)d_in[5];
    const float* Wv = (const float*)d_in[6];
    const float* bv = (const float*)d_in[7];
    float* H = (float*)d_out;

    static cudaStream_t s2 = nullptr;
    static cudaEvent_t evSplit = nullptr, evK = nullptr, evV = nullptr;
    if (!s2) {
        cudaFuncSetAttribute(tc_gemm, cudaFuncAttributeMaxDynamicSharedMemorySize, SMEM_TC);
        cudaStreamCreateWithFlags(&s2, cudaStreamNonBlocking);
        cudaEventCreateWithFlags(&evSplit, cudaEventDisableTiming);
        cudaEventCreateWithFlags(&evK, cudaEventDisableTiming);
        cudaEventCreateWithFlags(&evV, cudaEventDisableTiming);
    }

    // 0) fp32 -> split bf16 for X, Wq, Wk, Wv (main stream)
    {
        size_t n4 = NX / 4;
        split_sel<<<(unsigned)((n4 + 255) / 256), 256>>>(ebd, 0, n4);
        size_t w4 = (size_t)EE * EE / 4;
        split_sel<<<(unsigned)((w4 + 255) / 256), 256>>>(Wq, 1, w4);
        split_sel<<<(unsigned)((w4 + 255) / 256), 256>>>(Wk, 2, w4);
        split_sel<<<(unsigned)((w4 + 255) / 256), 256>>>(Wv, 3, w4);
    }
    cudaEventRecord(evSplit, 0);

    // s2: PROJK then PROJV (both masked, ~half CTAs exit); main: PROJQ
    cudaStreamWaitEvent(s2, evSplit, 0);
    tc_gemm<<<dim3(EE / 128, BB * (JMAX / 128), 1), 128, SMEM_TC, s2>>>(MODE_PROJK, seq, bk, nullptr);
    cudaEventRecord(evK, s2);
    tc_gemm<<<dim3(EE / 128, BB * (JMAX / 128), 1), 128, SMEM_TC, s2>>>(MODE_PROJV, seq, bv, nullptr);
    cudaEventRecord(evV, s2);

    tc_gemm<<<dim3(EE / 128, BB * SS / 128, 1), 128, SMEM_TC>>>(MODE_PROJQ, seq, bq, nullptr);

    // SCORE needs only K
    cudaStreamWaitEvent(0, evK, 0);

    // 2) scores -> exp splits + deterministic partial sums
    tc_gemm<<<dim3(JMAX / 128, SS / 128, BB), 128, SMEM_TC>>>(MODE_SCORE, seq, nullptr, nullptr);

    // 3) fold partials -> inv_l
    row_sums<<<(BB * SS + 255) / 256, 256>>>(seq);

    // PV needs V (PROJV hidden under PROJQ/SCORE)
    cudaStreamWaitEvent(0, evV, 0);

    // 4) H = (P @ V) * inv_l
    tc_gemm<<<dim3(EE / 128, SS / 128, BB), 128, SMEM_TC>>>(MODE_PV, seq, nullptr, H);
}

// round 17
// speedup vs baseline: 2.7495x; 2.3888x over previous
#include <cuda_runtime.h>
#include <cuda_fp16.h>
#include <cstdint>

#define BB 8
#define SS 4096
#define EE 768
#define JMAX 2048
#define INV_SQRT_DK 0.03608439182435161f

#define NX ((size_t)BB * SS * EE)     // 25.2M
#define NK ((size_t)BB * JMAX * EE)   // 12.6M
#define NP ((size_t)BB * SS * JMAX)   // 67.1M

// ---------------- scratch (device globals; no allocations allowed) ----------
__device__ __half g_X[NX];
__device__ __half g_Wq[EE * EE], g_Wk[EE * EE], g_Wv[EE * EE];
__device__ __half g_Q[NX];
__device__ __half g_K[NK];
__device__ __half g_Vt[NK];                       // [b][e][token] transposed V
__device__ __half g_P[NP];                        // unnormalized exp(P)
__device__ float g_partial[(size_t)BB * SS * 32]; // per-(row, ctile, wn) sums
__device__ float g_invl[BB * SS];                 // per-row 1/sum

// ---------------- helpers ----------------------------------------------------
__device__ __forceinline__ uint32_t smem_to_u32(const void* p) {
    uint32_t a;
    asm("{ .reg .u64 t; cvta.to.shared.u64 t, %1; cvt.u32.u64 %0, t; }" : "=r"(a) : "l"(p));
    return a;
}
__device__ __forceinline__ int seq_first(const int* __restrict__ s, int b) {
    const bool is64 = (s[1] == 0);
    int v = is64 ? s[4 * b] : s[2 * b];
    if (v < 1) v = 1;
    if (v > JMAX) v = JMAX;
    return v;
}
__device__ __forceinline__ uint32_t packh(__half a, __half b) {
    return (uint32_t)__half_as_ushort(a) | ((uint32_t)__half_as_ushort(b) << 16);
}

__device__ __forceinline__ void ldsm4(uint32_t* d, uint32_t a) {
    asm volatile("ldmatrix.sync.aligned.m8n8.x4.shared.b16 {%0,%1,%2,%3}, [%4];"
                 : "=r"(d[0]), "=r"(d[1]), "=r"(d[2]), "=r"(d[3]) : "r"(a));
}
__device__ __forceinline__ void mma_f16(float* c, const uint32_t* a, uint32_t b0, uint32_t b1) {
    asm volatile(
        "mma.sync.aligned.m16n8k16.row.col.f32.f16.f16.f32 "
        "{%0,%1,%2,%3}, {%4,%5,%6,%7}, {%8,%9}, {%0,%1,%2,%3};"
        : "+f"(c[0]), "+f"(c[1]), "+f"(c[2]), "+f"(c[3])
        : "r"(a[0]), "r"(a[1]), "r"(a[2]), "r"(a[3]), "r"(b0), "r"(b1));
}
#define CP_ASYNC16(sa, ga) \
    asm volatile("cp.async.cg.shared.global [%0], [%1], 16;" :: "r"(sa), "l"(ga) : "memory")
#define CP_COMMIT() asm volatile("cp.async.commit_group;" ::: "memory")
#define CP_WAIT(n)  asm volatile("cp.async.wait_group %0;" :: "n"(n) : "memory")

// ---------------- kernel: fp32 -> fp16 convert --------------------------------
__global__ __launch_bounds__(256) void cvt_sel(const float* __restrict__ src,
                                               int sel, size_t n4)
{
    size_t i = (size_t)blockIdx.x * 256 + threadIdx.x;
    if (i >= n4) return;
    __half* d;
    if (sel == 0)      d = g_X;
    else if (sel == 1) d = g_Wq;
    else if (sel == 2) d = g_Wk;
    else               d = g_Wv;
    float4 v = ((const float4*)src)[i];
    ((uint2*)d)[i] = make_uint2(packh(__float2half_rn(v.x), __float2half_rn(v.y)),
                                packh(__float2half_rn(v.z), __float2half_rn(v.w)));
}

// ---------------- generic fp16 NT GEMM on mma.sync ---------------------------
// D[128x128] = A[128xK] * B[128xK]^T, fp32 accumulate.
// 128 threads (4 warps, 2x2 grid, 64x64 warp tile), 3 CTAs/SM.
#define TSTRIDE 80
#define TILE_SM (128 * TSTRIDE)          // 10240
#define STAGE_SM (2 * TILE_SM)           // 20480
#define SMEM_TC (2 * STAGE_SM)           // 40960

#define MODE_PROJQ 0
#define MODE_PROJK 1
#define MODE_SCORE 2
#define MODE_PV    3
#define MODE_PROJV 4

__global__ __launch_bounds__(128, 3) void tc_gemm(int mode, const int* __restrict__ seq,
                                                  const float* __restrict__ bias,
                                                  float* __restrict__ Hout)
{
    const int n0 = blockIdx.x << 7;
    int b = 0, first = 0, Kdim = EE;
    size_t arow, brow, orow;
    int lda, ldb, ldo = EE;
    const __half *A, *B;
    float* outF = nullptr;
    __half* oH = nullptr;
    bool addb = false;
    int tloc = 0;

    if (mode == MODE_PROJQ) {
        arow = (size_t)blockIdx.y << 7; brow = n0; orow = arow;
        A = g_X; lda = EE; B = g_Wq; ldb = EE;
        oH = g_Q; ldo = EE; addb = true;
    } else if (mode == MODE_PROJK || mode == MODE_PROJV) {
        b = blockIdx.y >> 4;
        tloc = (blockIdx.y & 15) << 7;
        first = seq_first(seq, b);
        if (tloc >= first) return;
        arow = (size_t)b * SS + tloc; brow = n0; orow = (size_t)b * JMAX + tloc;
        A = g_X; lda = EE;
        B = (mode == MODE_PROJK) ? g_Wk : g_Wv;
        ldb = EE;
        oH = g_K; ldo = EE; addb = true;   // oH unused for PROJV
    } else if (mode == MODE_SCORE) {
        b = blockIdx.z; first = seq_first(seq, b);
        if (n0 >= first) return;
        arow = (size_t)b * SS + ((size_t)blockIdx.y << 7);
        brow = (size_t)b * JMAX + n0;
        A = g_Q; lda = EE; B = g_K; ldb = EE;
        oH = g_P; ldo = JMAX; orow = arow;
    } else { // MODE_PV
        b = blockIdx.z; first = seq_first(seq, b);
        Kdim = (first + 63) & ~63;
        arow = (size_t)b * SS + ((size_t)blockIdx.y << 7);
        brow = (size_t)b * EE + n0;
        A = g_P; lda = JMAX; B = g_Vt; ldb = JMAX;
        outF = Hout; ldo = EE; orow = arow;
    }

    extern __shared__ char smem[];
    const uint32_t sbase = smem_to_u32(smem);
    const int tid  = threadIdx.x;
    const int lane = tid & 31, wid = tid >> 5;
    const int wm = wid >> 1, wn = wid & 1;          // 2 x 2 warp grid, warp tile 64x64

    const char* gsrc[2] = { (const char*)(A + arow * lda), (const char*)(B + brow * ldb) };
    const size_t ldby[2] = { (size_t)lda * 2, (size_t)ldb * 2 };

    auto load_stage = [&](int s, int ki) {
        const size_t k0b = (size_t)ki * 64;          // 32 fp16 = 64 bytes
        const uint32_t sb = sbase + s * STAGE_SM;
        #pragma unroll
        for (int j = 0; j < 8; j++) {
            int t = tid + j * 128;                   // 1024 chunks of 16B
            int tile = t >> 9, row = (t >> 2) & 127, c = t & 3;
            uint32_t sa = sb + tile * TILE_SM + row * TSTRIDE + c * 16;
            const char* ga = gsrc[tile] + (size_t)row * ldby[tile] + k0b + c * 16;
            CP_ASYNC16(sa, ga);
        }
    };

    float acc[4][8][4];
    #pragma unroll
    for (int mt = 0; mt < 4; mt++)
        #pragma unroll
        for (int nt = 0; nt < 8; nt++)
            #pragma unroll
            for (int r = 0; r < 4; r++) acc[mt][nt][r] = 0.f;

    const int kt = Kdim >> 5;                        // BK = 32

    load_stage(0, 0);
    CP_COMMIT();

    for (int i = 0; i < kt; i++) {
        const int cur = i & 1;
        if (i + 1 < kt) { load_stage(cur ^ 1, i + 1); CP_COMMIT(); CP_WAIT(1); }
        else            { CP_WAIT(0); }
        __syncthreads();

        const uint32_t sb = sbase + cur * STAGE_SM;
        #pragma unroll
        for (int ks = 0; ks < 2; ks++) {             // two k16 halves of BK=32
            uint32_t ah[4][4];
            #pragma unroll
            for (int mt = 0; mt < 4; mt++) {
                uint32_t ra = sb + (wm * 64 + mt * 16 + (lane & 15)) * TSTRIDE
                            + ks * 32 + ((lane >> 4) << 4);
                ldsm4(ah[mt], ra);
            }
            uint32_t bh4[4][4];
            #pragma unroll
            for (int nt2 = 0; nt2 < 4; nt2++) {
                uint32_t rb = sb + TILE_SM
                            + (wn * 64 + nt2 * 16 + ((lane & 7) + ((lane >> 4) << 3))) * TSTRIDE
                            + ks * 32 + (((lane >> 3) & 1) << 4);
                ldsm4(bh4[nt2], rb);
            }
            #pragma unroll
            for (int mt = 0; mt < 4; mt++)
                #pragma unroll
                for (int nt2 = 0; nt2 < 4; nt2++)
                    #pragma unroll
                    for (int nn = 0; nn < 2; nn++)
                        mma_f16(acc[mt][nt2 * 2 + nn], ah[mt],
                                bh4[nt2][2 * nn], bh4[nt2][2 * nn + 1]);
        }
        __syncthreads();
    }

    // epilogue
    const int grp = lane >> 2, tig = lane & 3;
    #pragma unroll
    for (int mt = 0; mt < 4; mt++) {
        #pragma unroll
        for (int half_ = 0; half_ < 2; half_++) {
            const size_t row = orow + wm * 64 + mt * 16 + grp + half_ * 8;
            if (mode == MODE_SCORE) {
                float rsum = 0.f;
                #pragma unroll
                for (int nt = 0; nt < 8; nt++) {
                    const int col = n0 + wn * 64 + nt * 8 + tig * 2;
                    float p0 = 0.f, p1 = 0.f;
                    if (col >= 1 && col < first) {
                        p0 = __expf(acc[mt][nt][half_ * 2 + 0] * INV_SQRT_DK);
                        rsum += p0;
                    }
                    if (col + 1 >= 1 && col + 1 < first) {
                        p1 = __expf(acc[mt][nt][half_ * 2 + 1] * INV_SQRT_DK);
                        rsum += p1;
                    }
                    *(uint32_t*)&oH[row * ldo + col] =
                        packh(__float2half_rn(p0), __float2half_rn(p1));
                }
                rsum += __shfl_xor_sync(0xffffffff, rsum, 1);
                rsum += __shfl_xor_sync(0xffffffff, rsum, 2);
                if (tig == 0)
                    g_partial[row * 32 + (size_t)blockIdx.x * 2 + wn] = rsum;
            } else if (mode == MODE_PROJV) {
                // transposed write: Vt[b][e][token]
                const int tok = tloc + wm * 64 + mt * 16 + grp + half_ * 8;
                __half* vt = g_Vt + (size_t)b * EE * JMAX;
                #pragma unroll
                for (int nt = 0; nt < 8; nt++) {
                    const int col = n0 + wn * 64 + nt * 8 + tig * 2;
                    float v0 = acc[mt][nt][half_ * 2 + 0] + bias[col];
                    float v1 = acc[mt][nt][half_ * 2 + 1] + bias[col + 1];
                    vt[(size_t)col * JMAX + tok]       = __float2half_rn(v0);
                    vt[(size_t)(col + 1) * JMAX + tok] = __float2half_rn(v1);
                }
            } else if (outF) {   // PV
                const float rsc = g_invl[row];
                #pragma unroll
                for (int nt = 0; nt < 8; nt++) {
                    const int col = n0 + wn * 64 + nt * 8 + tig * 2;
                    *(float2*)&outF[row * ldo + col] =
                        make_float2(acc[mt][nt][half_ * 2 + 0] * rsc,
                                    acc[mt][nt][half_ * 2 + 1] * rsc);
                }
            } else {             // PROJQ / PROJK
                #pragma unroll
                for (int nt = 0; nt < 8; nt++) {
                    const int col = n0 + wn * 64 + nt * 8 + tig * 2;
                    float v0 = acc[mt][nt][half_ * 2 + 0];
                    float v1 = acc[mt][nt][half_ * 2 + 1];
                    if (addb) { v0 += bias[col]; v1 += bias[col + 1]; }
                    *(uint32_t*)&oH[row * ldo + col] =
                        packh(__float2half_rn(v0), __float2half_rn(v1));
                }
            }
        }
    }
}

// ---------------- kernel: fold partial sums -> inv_l -------------------------
__global__ __launch_bounds__(256) void row_sums(const int* __restrict__ seq)
{
    const int row = blockIdx.x * 256 + threadIdx.x;
    if (row >= BB * SS) return;
    const int b = row >> 12;
    const int first = seq_first(seq, b);
    const int np = 2 * ((first + 127) >> 7);
    const float* p = &g_partial[(size_t)row * 32];
    float s = 0.f;
    for (int i = 0; i < np; i++) s += p[i];
    g_invl[row] = 1.0f / fmaxf(s, 1e-30f);
}

// ---------------------------------------------------------------------------
extern "C" void kernel_launch(void* const* d_in, const int* in_sizes, int n_in,
                              void* d_out, int out_size)
{
    const float* ebd = (const float*)d_in[0];
    const int*   seq = (const int*)d_in[1];
    const float* Wq = (const float*)d_in[2];
    const float* bq = (const float*)d_in[3];
    const float* Wk = (const float*)d_in[4];
    const float* bk = (const float*)d_in[5];
    const float* Wv = (const float*)d_in[6];
    const float* bv = (const float*)d_in[7];
    float* H = (float*)d_out;

    static cudaStream_t s2 = nullptr;
    static cudaEvent_t evSplit = nullptr, evK = nullptr, evV = nullptr;
    if (!s2) {
        cudaFuncSetAttribute(tc_gemm, cudaFuncAttributeMaxDynamicSharedMemorySize, SMEM_TC);
        cudaStreamCreateWithFlags(&s2, cudaStreamNonBlocking);
        cudaEventCreateWithFlags(&evSplit, cudaEventDisableTiming);
        cudaEventCreateWithFlags(&evK, cudaEventDisableTiming);
        cudaEventCreateWithFlags(&evV, cudaEventDisableTiming);
    }

    // 0) fp32 -> fp16 for X, Wq, Wk, Wv
    {
        size_t n4 = NX / 4;
        cvt_sel<<<(unsigned)((n4 + 255) / 256), 256>>>(ebd, 0, n4);
        size_t w4 = (size_t)EE * EE / 4;
        cvt_sel<<<(unsigned)((w4 + 255) / 256), 256>>>(Wq, 1, w4);
        cvt_sel<<<(unsigned)((w4 + 255) / 256), 256>>>(Wk, 2, w4);
        cvt_sel<<<(unsigned)((w4 + 255) / 256), 256>>>(Wv, 3, w4);
    }
    cudaEventRecord(evSplit, 0);

    // s2: PROJK then PROJV (both masked); main: PROJQ
    cudaStreamWaitEvent(s2, evSplit, 0);
    tc_gemm<<<dim3(EE / 128, BB * (JMAX / 128), 1), 128, SMEM_TC, s2>>>(MODE_PROJK, seq, bk, nullptr);
    cudaEventRecord(evK, s2);
    tc_gemm<<<dim3(EE / 128, BB * (JMAX / 128), 1), 128, SMEM_TC, s2>>>(MODE_PROJV, seq, bv, nullptr);
    cudaEventRecord(evV, s2);

    tc_gemm<<<dim3(EE / 128, BB * SS / 128, 1), 128, SMEM_TC>>>(MODE_PROJQ, seq, bq, nullptr);

    // SCORE needs only K
    cudaStreamWaitEvent(0, evK, 0);

    // 2) scores -> exp(P) fp16 + deterministic partial sums
    tc_gemm<<<dim3(JMAX / 128, SS / 128, BB), 128, SMEM_TC>>>(MODE_SCORE, seq, nullptr, nullptr);

    // 3) fold partials -> inv_l
    row_sums<<<(BB * SS + 255) / 256, 256>>>(seq);

    // PV needs V (PROJV hidden under PROJQ/SCORE)
    cudaStreamWaitEvent(0, evV, 0);

    // 4) H = (P @ V) * inv_l
    tc_gemm<<<dim3(EE / 128, SS / 128, BB), 128, SMEM_TC>>>(MODE_PV, seq, nullptr, H);
}